// round 1
// baseline (speedup 1.0000x reference)
#include <cuda_runtime.h>
#include <math.h>

#define B_ 2
#define N_ 512
#define D_ 128
#define V_ 16
#define ROWS (B_*N_)

// scratch (allocation-free rule: __device__ globals)
__device__ float g_q [ROWS*D_];
__device__ float g_k [ROWS*D_];
__device__ float g_vv[ROWS*D_];
__device__ float g_qd[ROWS*D_];
__device__ float g_qdb[ROWS];

__device__ __forceinline__ float geluf(float x){
    return 0.5f*x*(1.0f+erff(x*0.70710678118654752f));
}
__device__ __forceinline__ float warpSum(float v){
    #pragma unroll
    for(int o=16;o;o>>=1) v += __shfl_down_sync(0xffffffffu, v, o);
    return v;
}
__device__ __forceinline__ float warpMax(float v){
    #pragma unroll
    for(int o=16;o;o>>=1) v = fmaxf(v, __shfl_down_sync(0xffffffffu, v, o));
    return v;
}
// 128-thread block reductions
__device__ __forceinline__ float blockSum(float v, float* red){
    int w = threadIdx.x>>5, l = threadIdx.x&31;
    v = warpSum(v);
    if(l==0) red[w]=v;
    __syncthreads();
    if(threadIdx.x==0) red[0] = red[0]+red[1]+red[2]+red[3];
    __syncthreads();
    float r = red[0];
    __syncthreads();
    return r;
}
__device__ __forceinline__ float blockMax(float v, float* red){
    int w = threadIdx.x>>5, l = threadIdx.x&31;
    v = warpMax(v);
    if(l==0) red[w]=v;
    __syncthreads();
    if(threadIdx.x==0) red[0] = fmaxf(fmaxf(red[0],red[1]), fmaxf(red[2],red[3]));
    __syncthreads();
    float r = red[0];
    __syncthreads();
    return r;
}

// ---------------- Kernel A: LN + q/k/v + qd = W_d2 q, qdb = q.b_d2 ----------
__global__ void __launch_bounds__(128) prep_kernel(
    const float* __restrict__ scalar,
    const float* __restrict__ w_q, const float* __restrict__ b_q,
    const float* __restrict__ w_k, const float* __restrict__ b_k,
    const float* __restrict__ w_v, const float* __restrict__ b_v,
    const float* __restrict__ w_d2, const float* __restrict__ b_d2,
    const float* __restrict__ g_s, const float* __restrict__ be_s)
{
    __shared__ float ssn[D_], sq[D_], red[4];
    const int row = blockIdx.x;
    const int d = threadIdx.x;

    float x = scalar[row*D_+d];
    float m  = blockSum(x, red)*(1.0f/D_);
    float dv = x - m;
    float var= blockSum(dv*dv, red)*(1.0f/D_);
    float sn = dv*rsqrtf(var+1e-5f)*g_s[d] + be_s[d];
    ssn[d]=sn;
    __syncthreads();

    float q=b_q[d], k=b_k[d], v=b_v[d];
    #pragma unroll 4
    for(int e=0;e<D_;e++){
        float s = ssn[e];
        q = fmaf(s, w_q[e*D_+d], q);
        k = fmaf(s, w_k[e*D_+d], k);
        v = fmaf(s, w_v[e*D_+d], v);
    }
    g_q [row*D_+d]=q;
    g_k [row*D_+d]=k;
    g_vv[row*D_+d]=v;
    sq[d]=q;
    __syncthreads();

    // qd[e] = sum_d w_d2[e,d]*q[d]  (thread index = e)
    float qd=0;
    #pragma unroll 4
    for(int e2=0;e2<D_;e2++) qd = fmaf(sq[e2], w_d2[d*D_+e2], qd);
    g_qd[row*D_+d]=qd;

    float pb = blockSum(q*b_d2[d], red);
    if(d==0) g_qdb[row]=pb;
}

// ---------------- Kernel B: attention + all epilogues, one row per block ----
__global__ void __launch_bounds__(128) main_kernel(
    const float* __restrict__ scalar, const float* __restrict__ vector,
    const float* __restrict__ coords,
    const float* __restrict__ w_d1, const float* __restrict__ b_d1,
    const float* __restrict__ w_d2, const float* __restrict__ b_d2,
    const float* __restrict__ w_g,  const float* __restrict__ b_g,
    const float* __restrict__ w_o,  const float* __restrict__ b_o,
    const float* __restrict__ w_f1, const float* __restrict__ b_f1,
    const float* __restrict__ w_f2, const float* __restrict__ b_f2,
    const float* __restrict__ w_vo, const float* __restrict__ b_vo,
    const float* __restrict__ g_s,  const float* __restrict__ be_s,
    const float* __restrict__ g_v_, const float* __restrict__ be_v,
    float* __restrict__ out_scalar, float* __restrict__ out_vector)
{
    __shared__ float sq[D_], sqd[D_], w1s[D_], b1s[D_];
    __shared__ float sdist[N_], slog[N_];
    __shared__ float sH[D_], sbuf[D_], sscal[D_], shn[D_], sf[2*D_];
    __shared__ float svagg[48], sdir[3], sgate[V_], sagg[48];
    __shared__ float red[4];

    const int row  = blockIdx.x;
    const int b    = row >> 9;
    const int i    = row & (N_-1);
    const int tid  = threadIdx.x;
    const int warp = tid>>5, lane = tid&31;

    sq [tid] = g_q [row*D_+tid];
    sqd[tid] = g_qd[row*D_+tid];
    w1s[tid] = w_d1[tid];
    b1s[tid] = b_d1[tid];
    const float qdb = g_qdb[row];
    const float ci0 = coords[row*3+0], ci1 = coords[row*3+1], ci2 = coords[row*3+2];
    __syncthreads();

    const float* kb   = g_k  + (size_t)b*N_*D_;
    const float* vvb  = g_vv + (size_t)b*N_*D_;
    const float* vecb = vector + (size_t)b*N_*3*V_;
    const float* cb   = coords + (size_t)b*N_*3;
    const float invS  = 0.0883883476483184f; // 1/sqrt(128)

    // ---- pass 1: logits (warp per j, lane per d-chunk) ----
    for(int j=warp; j<N_; j+=4){
        float cj0=cb[j*3+0], cj1=cb[j*3+1], cj2=cb[j*3+2];
        float dx=ci0-cj0, dy=ci1-cj1, dz=ci2-cj2;
        float dist = sqrtf(dx*dx+dy*dy+dz*dz);
        if(lane==0) sdist[j]=dist;
        float s=0.0f;
        #pragma unroll
        for(int c=0;c<4;c++){
            int d = lane + 32*c;
            float kk = kb[j*D_+d];
            float h  = geluf(fmaf(dist, w1s[d], b1s[d]));
            s += sq[d]*kk + sqd[d]*h;
        }
        s = warpSum(s);
        if(lane==0) slog[j] = (s + qdb)*invS;
    }
    __syncthreads();

    // ---- softmax over j ----
    float mx = -1e30f;
    for(int j=tid;j<N_;j+=128) mx = fmaxf(mx, slog[j]);
    mx = blockMax(mx, red);
    float sum=0.0f;
    for(int j=tid;j<N_;j+=128){ float e=expf(slog[j]-mx); slog[j]=e; sum+=e; }
    sum = blockSum(sum, red);
    float inv = 1.0f/sum;
    for(int j=tid;j<N_;j+=128) slog[j]*=inv;
    __syncthreads();

    // ---- pass 2: H = sum attn*h, Vd = sum attn*v  (thread per d) ----
    const float w1d = w1s[tid], b1d = b1s[tid];
    float H=0.0f, Vd=0.0f;
    #pragma unroll 4
    for(int j=0;j<N_;j++){
        float a = slog[j];
        float dist = sdist[j];
        H  = fmaf(a, geluf(fmaf(dist, w1d, b1d)), H);
        Vd = fmaf(a, vvb[j*D_+tid], Vd);
    }
    sH[tid]=H;

    // ---- vector aggregation + direction aggregation ----
    if(tid<48){
        float acc=0.0f;
        #pragma unroll 4
        for(int j=0;j<N_;j++) acc = fmaf(slog[j], vecb[j*3*V_+tid], acc);
        svagg[tid]=acc;
    } else if(tid<51){
        int c = tid-48;
        float cic = (c==0)?ci0:((c==1)?ci1:ci2);
        float acc=0.0f;
        for(int j=0;j<N_;j++){
            float cj = cb[j*3+c];
            acc += slog[j]*(cic-cj)/fmaxf(sdist[j],1e-6f);
        }
        sdir[c]=acc;
    }
    __syncthreads();

    // ---- upd = attn@v + H@w_d2 + b_d2 ----
    float upd = Vd + b_d2[tid];
    #pragma unroll 4
    for(int e=0;e<D_;e++) upd = fmaf(sH[e], w_d2[e*D_+tid], upd);
    sbuf[tid]=upd;
    __syncthreads();

    // ---- scalar1 = scalar + upd@w_o + b_o ----
    float s1 = scalar[row*D_+tid] + b_o[tid];
    #pragma unroll 4
    for(int e=0;e<D_;e++) s1 = fmaf(sbuf[e], w_o[e*D_+tid], s1);
    sscal[tid]=s1;

    // ---- LN ----
    float m  = blockSum(s1, red)*(1.0f/D_);
    float dv = s1 - m;
    float var= blockSum(dv*dv, red)*(1.0f/D_);
    float hn = dv*rsqrtf(var+1e-5f)*g_s[tid] + be_s[tid];
    shn[tid]=hn;
    __syncthreads();

    // ---- FFN ----
    for(int m2=tid; m2<2*D_; m2+=128){
        float a = b_f1[m2];
        #pragma unroll 4
        for(int e=0;e<D_;e++) a = fmaf(shn[e], w_f1[e*2*D_+m2], a);
        sf[m2]=geluf(a);
    }
    __syncthreads();

    float s2 = sscal[tid] + b_f2[tid];
    #pragma unroll 4
    for(int m2=0;m2<2*D_;m2++) s2 = fmaf(sf[m2], w_f2[m2*D_+tid], s2);
    out_scalar[row*D_+tid] = s2;
    sscal[tid] = s2;
    __syncthreads();

    // ---- gate ----
    if(tid<V_){
        float a = b_g[tid];
        #pragma unroll 4
        for(int d2=0;d2<D_;d2++) a = fmaf(sscal[d2], w_g[d2*V_+tid], a);
        sgate[tid] = 1.0f/(1.0f+expf(-a));
    }
    __syncthreads();

    // ---- agg, LN over V, proj, vector residual ----
    if(tid<48){
        int c = tid>>4, vv = tid&15;
        sagg[tid] = svagg[tid] + sdir[c]*sgate[vv];
    }
    __syncthreads();
    if(tid<48){
        int c = tid>>4, vv = tid&15;
        float m2=0.0f;
        #pragma unroll
        for(int u=0;u<V_;u++) m2 += sagg[c*V_+u];
        m2 *= (1.0f/V_);
        float var2=0.0f;
        #pragma unroll
        for(int u=0;u<V_;u++){ float d3=sagg[c*V_+u]-m2; var2 += d3*d3; }
        var2 *= (1.0f/V_);
        float invr = rsqrtf(var2+1e-5f);
        float acc = b_vo[vv];
        #pragma unroll
        for(int u=0;u<V_;u++){
            float lnu = (sagg[c*V_+u]-m2)*invr*g_v_[u] + be_v[u];
            acc = fmaf(lnu, w_vo[u*V_+vv], acc);
        }
        out_vector[row*3*V_+tid] = vecb[i*3*V_+tid] + acc;
    }
}

extern "C" void kernel_launch(void* const* d_in, const int* in_sizes, int n_in,
                              void* d_out, int out_size)
{
    const float* scalar = (const float*)d_in[0];
    const float* vector = (const float*)d_in[1];
    const float* coords = (const float*)d_in[2];
    const float* w_q  = (const float*)d_in[3];  const float* b_q  = (const float*)d_in[4];
    const float* w_k  = (const float*)d_in[5];  const float* b_k  = (const float*)d_in[6];
    const float* w_v  = (const float*)d_in[7];  const float* b_v  = (const float*)d_in[8];
    const float* w_d1 = (const float*)d_in[9];  const float* b_d1 = (const float*)d_in[10];
    const float* w_d2 = (const float*)d_in[11]; const float* b_d2 = (const float*)d_in[12];
    const float* w_g  = (const float*)d_in[13]; const float* b_g  = (const float*)d_in[14];
    const float* w_o  = (const float*)d_in[15]; const float* b_o  = (const float*)d_in[16];
    const float* w_f1 = (const float*)d_in[17]; const float* b_f1 = (const float*)d_in[18];
    const float* w_f2 = (const float*)d_in[19]; const float* b_f2 = (const float*)d_in[20];
    const float* w_vo = (const float*)d_in[21]; const float* b_vo = (const float*)d_in[22];
    const float* g_s  = (const float*)d_in[23]; const float* be_s = (const float*)d_in[24];
    const float* g_v  = (const float*)d_in[25]; const float* be_v = (const float*)d_in[26];

    float* out = (float*)d_out;
    float* out_scalar = out;
    float* out_vector = out + (size_t)ROWS*D_;

    prep_kernel<<<ROWS,128>>>(scalar, w_q,b_q, w_k,b_k, w_v,b_v, w_d2,b_d2, g_s,be_s);
    main_kernel<<<ROWS,128>>>(scalar, vector, coords,
                              w_d1,b_d1, w_d2,b_d2, w_g,b_g, w_o,b_o,
                              w_f1,b_f1, w_f2,b_f2, w_vo,b_vo,
                              g_s,be_s, g_v,be_v,
                              out_scalar, out_vector);
}

// round 2
// speedup vs baseline: 1.6941x; 1.6941x over previous
#include <cuda_runtime.h>
#include <math.h>

#define B_ 2
#define N_ 512
#define D_ 128
#define V_ 16
#define ROWS (B_*N_)

// scratch (allocation-free rule: __device__ globals)
__device__ float g_q [ROWS*D_];
__device__ float g_k [ROWS*D_];
__device__ float g_vv[ROWS*D_];
__device__ float g_qd[ROWS*D_];
__device__ float g_qdb[ROWS];

__device__ __forceinline__ float geluf(float x){
    return 0.5f*x*(1.0f+erff(x*0.70710678118654752f));
}
__device__ __forceinline__ float warpSum(float v){
    #pragma unroll
    for(int o=16;o;o>>=1) v += __shfl_down_sync(0xffffffffu, v, o);
    return v;
}
// 128-thread block reduction
__device__ __forceinline__ float blockSum(float v, float* red){
    int w = threadIdx.x>>5, l = threadIdx.x&31;
    v = warpSum(v);
    if(l==0) red[w]=v;
    __syncthreads();
    if(threadIdx.x==0) red[0] = red[0]+red[1]+red[2]+red[3];
    __syncthreads();
    float r = red[0];
    __syncthreads();
    return r;
}

// ---------------- Kernel A: LN + q/k/v + qd = W_d2 q, qdb = q.b_d2 ----------
__global__ void __launch_bounds__(128) prep_kernel(
    const float* __restrict__ scalar,
    const float* __restrict__ w_q, const float* __restrict__ b_q,
    const float* __restrict__ w_k, const float* __restrict__ b_k,
    const float* __restrict__ w_v, const float* __restrict__ b_v,
    const float* __restrict__ w_d2, const float* __restrict__ b_d2,
    const float* __restrict__ g_s, const float* __restrict__ be_s)
{
    __shared__ float ssn[D_], sq[D_], red[4];
    const int row = blockIdx.x;
    const int d = threadIdx.x;

    float x = scalar[row*D_+d];
    float m  = blockSum(x, red)*(1.0f/D_);
    float dv = x - m;
    float var= blockSum(dv*dv, red)*(1.0f/D_);
    float sn = dv*rsqrtf(var+1e-5f)*g_s[d] + be_s[d];
    ssn[d]=sn;
    __syncthreads();

    float q0=0,q1=0,k0=0,k1=0,v0=0,v1=0;
    #pragma unroll 4
    for(int e=0;e<D_;e+=2){
        float s0 = ssn[e], s1 = ssn[e+1];
        q0 = fmaf(s0, w_q[e*D_+d], q0);      q1 = fmaf(s1, w_q[(e+1)*D_+d], q1);
        k0 = fmaf(s0, w_k[e*D_+d], k0);      k1 = fmaf(s1, w_k[(e+1)*D_+d], k1);
        v0 = fmaf(s0, w_v[e*D_+d], v0);      v1 = fmaf(s1, w_v[(e+1)*D_+d], v1);
    }
    float q = q0+q1+b_q[d];
    g_q [row*D_+d]=q;
    g_k [row*D_+d]=k0+k1+b_k[d];
    g_vv[row*D_+d]=v0+v1+b_v[d];
    sq[d]=q;
    __syncthreads();

    // qd[e] = sum_d w_d2[e,d]*q[d]  (thread index = e)
    float a0=0,a1=0,a2=0,a3=0;
    #pragma unroll 4
    for(int e2=0;e2<D_;e2+=4){
        a0 = fmaf(sq[e2+0], w_d2[d*D_+e2+0], a0);
        a1 = fmaf(sq[e2+1], w_d2[d*D_+e2+1], a1);
        a2 = fmaf(sq[e2+2], w_d2[d*D_+e2+2], a2);
        a3 = fmaf(sq[e2+3], w_d2[d*D_+e2+3], a3);
    }
    g_qd[row*D_+d]=(a0+a1)+(a2+a3);

    float pb = blockSum(q*b_d2[d], red);
    if(d==0) g_qdb[row]=pb;
}

// ---------------- Kernel B: fused attention + all epilogues, one row/block --
__global__ void __launch_bounds__(128) main_kernel(
    const float* __restrict__ scalar, const float* __restrict__ vector,
    const float* __restrict__ coords,
    const float* __restrict__ w_d1, const float* __restrict__ b_d1,
    const float* __restrict__ w_d2, const float* __restrict__ b_d2,
    const float* __restrict__ w_g,  const float* __restrict__ b_g,
    const float* __restrict__ w_o,  const float* __restrict__ b_o,
    const float* __restrict__ w_f1, const float* __restrict__ b_f1,
    const float* __restrict__ w_f2, const float* __restrict__ b_f2,
    const float* __restrict__ w_vo, const float* __restrict__ b_vo,
    const float* __restrict__ g_s,  const float* __restrict__ be_s,
    const float* __restrict__ g_v_, const float* __restrict__ be_v,
    float* __restrict__ out_scalar, float* __restrict__ out_vector)
{
    __shared__ float sq[D_], sqd[D_];
    __shared__ float scoord[N_*3];
    __shared__ float sdist[N_], slog[N_];
    __shared__ float sHm[4][D_], sVm[4][D_];
    __shared__ float sSum[4];
    __shared__ float sH[D_], sbuf[D_], sscal[D_], shn[D_], sf[2*D_];
    __shared__ float svagg2[96], sdirp[24], sdir[3], sgate[V_], sagg[48], svagg[48];
    __shared__ float red[4];

    const int row  = blockIdx.x;
    const int b    = row >> 9;
    const int i    = row & (N_-1);
    const int tid  = threadIdx.x;
    const int warp = tid>>5, lane = tid&31;
    const int half = lane>>4, hl = lane&15;

    sq [tid] = g_q [row*D_+tid];
    sqd[tid] = g_qd[row*D_+tid];
    const float* cb = coords + (size_t)b*N_*3;
    for(int t=tid; t<N_*3; t+=128) scoord[t]=cb[t];
    const float invS = 0.0883883476483184f; // 1/sqrt(128)
    const float qdbS = g_qdb[row]*invS;
    __syncthreads();

    const float ci0 = scoord[i*3+0], ci1 = scoord[i*3+1], ci2 = scoord[i*3+2];

    const float* kb   = g_k  + (size_t)b*N_*D_;
    const float* vvb  = g_vv + (size_t)b*N_*D_;
    const float* vecb = vector + (size_t)b*N_*3*V_;

    // per-lane constants: d = hl*8 + c
    float qr[8], qdr[8], w1r[8], b1r[8];
    {
        const float4* p;
        p=(const float4*)sq;   float4 a=p[hl*2], bb=p[hl*2+1];
        qr[0]=a.x;qr[1]=a.y;qr[2]=a.z;qr[3]=a.w; qr[4]=bb.x;qr[5]=bb.y;qr[6]=bb.z;qr[7]=bb.w;
        p=(const float4*)sqd;  a=p[hl*2]; bb=p[hl*2+1];
        qdr[0]=a.x;qdr[1]=a.y;qdr[2]=a.z;qdr[3]=a.w; qdr[4]=bb.x;qdr[5]=bb.y;qdr[6]=bb.z;qdr[7]=bb.w;
        p=(const float4*)w_d1; a=p[hl*2]; bb=p[hl*2+1];
        w1r[0]=a.x;w1r[1]=a.y;w1r[2]=a.z;w1r[3]=a.w; w1r[4]=bb.x;w1r[5]=bb.y;w1r[6]=bb.z;w1r[7]=bb.w;
        p=(const float4*)b_d1; a=p[hl*2]; bb=p[hl*2+1];
        b1r[0]=a.x;b1r[1]=a.y;b1r[2]=a.z;b1r[3]=a.w; b1r[4]=bb.x;b1r[5]=bb.y;b1r[6]=bb.z;b1r[7]=bb.w;
    }

    // ---- single fused pass: 2 j's per warp-iter (16 lanes each, 8 d's/lane)
    float Hc[8]={0,0,0,0,0,0,0,0}, Vc[8]={0,0,0,0,0,0,0,0};
    float sacc = 0.0f;

    for(int base = warp*2; base < N_; base += 8){
        const int j = base + half;
        // dist
        float dx = ci0 - scoord[j*3+0];
        float dy = ci1 - scoord[j*3+1];
        float dz = ci2 - scoord[j*3+2];
        float dist = sqrtf(fmaf(dx,dx,fmaf(dy,dy,dz*dz)));

        // k & v rows (coalesced float4)
        const float4* krow = (const float4*)(kb + (size_t)j*D_);
        const float4* vrow = (const float4*)(vvb + (size_t)j*D_);
        float4 ka = krow[hl*2], kb4 = krow[hl*2+1];
        float4 va = vrow[hl*2], vb4 = vrow[hl*2+1];
        float kr[8] = {ka.x,ka.y,ka.z,ka.w,kb4.x,kb4.y,kb4.z,kb4.w};
        float vr[8] = {va.x,va.y,va.z,va.w,vb4.x,vb4.y,vb4.z,vb4.w};

        float hh[8];
        float p = 0.0f;
        #pragma unroll
        for(int c=0;c<8;c++){
            hh[c] = geluf(fmaf(dist, w1r[c], b1r[c]));
            p = fmaf(qr[c], kr[c], p);
            p = fmaf(qdr[c], hh[c], p);
        }
        // reduce over the 16-lane group
        p += __shfl_xor_sync(0xffffffffu, p, 8);
        p += __shfl_xor_sync(0xffffffffu, p, 4);
        p += __shfl_xor_sync(0xffffffffu, p, 2);
        p += __shfl_xor_sync(0xffffffffu, p, 1);

        float e = __expf(fmaf(p, invS, qdbS));
        if(hl==0){ slog[j]=e; sdist[j]=dist; }
        sacc += e;

        #pragma unroll
        for(int c=0;c<8;c++){
            Hc[c] = fmaf(e, hh[c], Hc[c]);
            Vc[c] = fmaf(e, vr[c], Vc[c]);
        }
    }

    // merge halves within warp
    #pragma unroll
    for(int c=0;c<8;c++){
        Hc[c] += __shfl_xor_sync(0xffffffffu, Hc[c], 16);
        Vc[c] += __shfl_xor_sync(0xffffffffu, Vc[c], 16);
    }
    sacc += __shfl_xor_sync(0xffffffffu, sacc, 16);
    if(half==0){
        #pragma unroll
        for(int c=0;c<8;c++){ sHm[warp][hl*8+c]=Hc[c]; sVm[warp][hl*8+c]=Vc[c]; }
    }
    if(lane==0) sSum[warp]=sacc;
    __syncthreads();

    // merge warps + normalize
    const float inv = 1.0f/(sSum[0]+sSum[1]+sSum[2]+sSum[3]);
    float Hd = (sHm[0][tid]+sHm[1][tid]+sHm[2][tid]+sHm[3][tid])*inv;
    float Vd = (sVm[0][tid]+sVm[1][tid]+sVm[2][tid]+sVm[3][tid])*inv;
    sH[tid]=Hd;
    for(int j=tid;j<N_;j+=128) slog[j]*=inv;
    __syncthreads();

    // ---- vector aggregation (96 thr) + direction aggregation (24 thr) ----
    if(tid < 96){
        const int t48 = (tid<48)?tid:(tid-48);
        const int j0  = (tid<48)?0:256;
        float a0=0,a1=0;
        #pragma unroll 4
        for(int j=j0;j<j0+256;j+=2){
            a0 = fmaf(slog[j],   vecb[(size_t)j*48+t48],     a0);
            a1 = fmaf(slog[j+1], vecb[(size_t)(j+1)*48+t48], a1);
        }
        svagg2[tid]=a0+a1;
    } else if(tid < 120){
        const int idx = tid-96, c = idx>>3, g = idx&7;
        const float cic = scoord[i*3+c];
        float acc=0.0f;
        for(int j=g;j<N_;j+=8){
            float d = fmaxf(sdist[j],1e-6f);
            acc += slog[j]*__fdividef(cic - scoord[j*3+c], d);
        }
        sdirp[idx]=acc;
    }
    __syncthreads();
    if(tid<48) svagg[tid]=svagg2[tid]+svagg2[tid+48];
    if(tid<3){
        float a=0;
        #pragma unroll
        for(int g=0;g<8;g++) a+=sdirp[tid*8+g];
        sdir[tid]=a;
    }

    // ---- upd = attn@v + H@w_d2 + b_d2 ----
    {
        float u0=0,u1=0,u2=0,u3=0;
        #pragma unroll 4
        for(int e=0;e<D_;e+=4){
            u0 = fmaf(sH[e+0], w_d2[(e+0)*D_+tid], u0);
            u1 = fmaf(sH[e+1], w_d2[(e+1)*D_+tid], u1);
            u2 = fmaf(sH[e+2], w_d2[(e+2)*D_+tid], u2);
            u3 = fmaf(sH[e+3], w_d2[(e+3)*D_+tid], u3);
        }
        sbuf[tid] = Vd + b_d2[tid] + ((u0+u1)+(u2+u3));
    }
    __syncthreads();

    // ---- scalar1 = scalar + upd@w_o + b_o ----
    float s1;
    {
        float u0=0,u1=0,u2=0,u3=0;
        #pragma unroll 4
        for(int e=0;e<D_;e+=4){
            u0 = fmaf(sbuf[e+0], w_o[(e+0)*D_+tid], u0);
            u1 = fmaf(sbuf[e+1], w_o[(e+1)*D_+tid], u1);
            u2 = fmaf(sbuf[e+2], w_o[(e+2)*D_+tid], u2);
            u3 = fmaf(sbuf[e+3], w_o[(e+3)*D_+tid], u3);
        }
        s1 = scalar[row*D_+tid] + b_o[tid] + ((u0+u1)+(u2+u3));
    }
    sscal[tid]=s1;

    // ---- LN ----
    float m  = blockSum(s1, red)*(1.0f/D_);
    float dv = s1 - m;
    float var= blockSum(dv*dv, red)*(1.0f/D_);
    float hn = dv*rsqrtf(var+1e-5f)*g_s[tid] + be_s[tid];
    shn[tid]=hn;
    __syncthreads();

    // ---- FFN layer 1 (each thread: m2 = tid, tid+128) ----
    #pragma unroll
    for(int h2=0; h2<2; h2++){
        int m2 = tid + h2*128;
        float u0=0,u1=0,u2=0,u3=0;
        #pragma unroll 4
        for(int e=0;e<D_;e+=4){
            u0 = fmaf(shn[e+0], w_f1[(e+0)*2*D_+m2], u0);
            u1 = fmaf(shn[e+1], w_f1[(e+1)*2*D_+m2], u1);
            u2 = fmaf(shn[e+2], w_f1[(e+2)*2*D_+m2], u2);
            u3 = fmaf(shn[e+3], w_f1[(e+3)*2*D_+m2], u3);
        }
        sf[m2]=geluf(b_f1[m2] + (u0+u1)+(u2+u3));
    }
    __syncthreads();

    // ---- FFN layer 2 ----
    float s2;
    {
        float u0=0,u1=0,u2=0,u3=0;
        #pragma unroll 4
        for(int m2=0;m2<2*D_;m2+=4){
            u0 = fmaf(sf[m2+0], w_f2[(m2+0)*D_+tid], u0);
            u1 = fmaf(sf[m2+1], w_f2[(m2+1)*D_+tid], u1);
            u2 = fmaf(sf[m2+2], w_f2[(m2+2)*D_+tid], u2);
            u3 = fmaf(sf[m2+3], w_f2[(m2+3)*D_+tid], u3);
        }
        s2 = sscal[tid] + b_f2[tid] + ((u0+u1)+(u2+u3));
    }
    out_scalar[row*D_+tid] = s2;
    __syncthreads();
    sscal[tid] = s2;
    __syncthreads();

    // ---- gate ----
    if(tid<V_){
        float u0=0,u1=0,u2=0,u3=0;
        #pragma unroll 4
        for(int d2=0;d2<D_;d2+=4){
            u0 = fmaf(sscal[d2+0], w_g[(d2+0)*V_+tid], u0);
            u1 = fmaf(sscal[d2+1], w_g[(d2+1)*V_+tid], u1);
            u2 = fmaf(sscal[d2+2], w_g[(d2+2)*V_+tid], u2);
            u3 = fmaf(sscal[d2+3], w_g[(d2+3)*V_+tid], u3);
        }
        float a = b_g[tid] + (u0+u1)+(u2+u3);
        sgate[tid] = 1.0f/(1.0f+__expf(-a));
    }
    __syncthreads();

    // ---- agg, LN over V, proj, vector residual ----
    if(tid<48){
        int c = tid>>4, vv = tid&15;
        sagg[tid] = svagg[tid] + sdir[c]*sgate[vv];
    }
    __syncthreads();
    if(tid<48){
        int c = tid>>4, vv = tid&15;
        float m2=0.0f;
        #pragma unroll
        for(int u=0;u<V_;u++) m2 += sagg[c*V_+u];
        m2 *= (1.0f/V_);
        float var2=0.0f;
        #pragma unroll
        for(int u=0;u<V_;u++){ float d3=sagg[c*V_+u]-m2; var2 += d3*d3; }
        var2 *= (1.0f/V_);
        float invr = rsqrtf(var2+1e-5f);
        float acc = b_vo[vv];
        #pragma unroll
        for(int u=0;u<V_;u++){
            float lnu = (sagg[c*V_+u]-m2)*invr*g_v_[u] + be_v[u];
            acc = fmaf(lnu, w_vo[u*V_+vv], acc);
        }
        out_vector[row*3*V_+tid] = vecb[(size_t)i*3*V_+tid] + acc;
    }
}

extern "C" void kernel_launch(void* const* d_in, const int* in_sizes, int n_in,
                              void* d_out, int out_size)
{
    const float* scalar = (const float*)d_in[0];
    const float* vector = (const float*)d_in[1];
    const float* coords = (const float*)d_in[2];
    const float* w_q  = (const float*)d_in[3];  const float* b_q  = (const float*)d_in[4];
    const float* w_k  = (const float*)d_in[5];  const float* b_k  = (const float*)d_in[6];
    const float* w_v  = (const float*)d_in[7];  const float* b_v  = (const float*)d_in[8];
    const float* w_d1 = (const float*)d_in[9];  const float* b_d1 = (const float*)d_in[10];
    const float* w_d2 = (const float*)d_in[11]; const float* b_d2 = (const float*)d_in[12];
    const float* w_g  = (const float*)d_in[13]; const float* b_g  = (const float*)d_in[14];
    const float* w_o  = (const float*)d_in[15]; const float* b_o  = (const float*)d_in[16];
    const float* w_f1 = (const float*)d_in[17]; const float* b_f1 = (const float*)d_in[18];
    const float* w_f2 = (const float*)d_in[19]; const float* b_f2 = (const float*)d_in[20];
    const float* w_vo = (const float*)d_in[21]; const float* b_vo = (const float*)d_in[22];
    const float* g_s  = (const float*)d_in[23]; const float* be_s = (const float*)d_in[24];
    const float* g_v  = (const float*)d_in[25]; const float* be_v = (const float*)d_in[26];

    float* out = (float*)d_out;
    float* out_scalar = out;
    float* out_vector = out + (size_t)ROWS*D_;

    prep_kernel<<<ROWS,128>>>(scalar, w_q,b_q, w_k,b_k, w_v,b_v, w_d2,b_d2, g_s,be_s);
    main_kernel<<<ROWS,128>>>(scalar, vector, coords,
                              w_d1,b_d1, w_d2,b_d2, w_g,b_g, w_o,b_o,
                              w_f1,b_f1, w_f2,b_f2, w_vo,b_vo,
                              g_s,be_s, g_v,be_v,
                              out_scalar, out_vector);
}

// round 3
// speedup vs baseline: 1.8352x; 1.0833x over previous
#include <cuda_runtime.h>
#include <math.h>

#define B_ 2
#define N_ 512
#define D_ 128
#define V_ 16
#define ROWS (B_*N_)

// scratch (allocation-free rule: __device__ globals)
__device__ float g_q [ROWS*D_];
__device__ float g_k [ROWS*D_];
__device__ float g_vv[ROWS*D_];
__device__ float g_qd[ROWS*D_];
__device__ float g_qdb[ROWS];

__device__ __forceinline__ float geluf(float x){
    return 0.5f*x*(1.0f+erff(x*0.70710678118654752f));
}
// exact-gelu Taylor (|x| <~ 1.2): gelu = x*(0.5 + k*x*P(x^2)), err < 2e-5
__device__ __forceinline__ float gelu_fast(float x){
    float u = x*x;
    float P = fmaf(u, fmaf(u, fmaf(u, fmaf(u,
                2.8935185185185e-4f, -2.9761904761905e-3f),
                0.025f), -0.16666666666667f), 1.0f);
    return x * fmaf(0.3989422804014327f*x, P, 0.5f);
}
__device__ __forceinline__ float warpSum(float v){
    #pragma unroll
    for(int o=16;o;o>>=1) v += __shfl_down_sync(0xffffffffu, v, o);
    return v;
}
__device__ __forceinline__ float blockSum(float v, float* red){
    int w = threadIdx.x>>5, l = threadIdx.x&31;
    v = warpSum(v);
    if(l==0) red[w]=v;
    __syncthreads();
    if(threadIdx.x==0) red[0] = red[0]+red[1]+red[2]+red[3];
    __syncthreads();
    float r = red[0];
    __syncthreads();
    return r;
}

// ---------------- Kernel A: LN + q/k/v + qd = W_d2 q, qdb = q.b_d2 ----------
__global__ void __launch_bounds__(128) prep_kernel(
    const float* __restrict__ scalar,
    const float* __restrict__ w_q, const float* __restrict__ b_q,
    const float* __restrict__ w_k, const float* __restrict__ b_k,
    const float* __restrict__ w_v, const float* __restrict__ b_v,
    const float* __restrict__ w_d2, const float* __restrict__ b_d2,
    const float* __restrict__ g_s, const float* __restrict__ be_s)
{
    __shared__ float ssn[D_], sq[D_], red[4];
    const int row = blockIdx.x;
    const int d = threadIdx.x;

    float x = scalar[row*D_+d];
    float m  = blockSum(x, red)*(1.0f/D_);
    float dv = x - m;
    float var= blockSum(dv*dv, red)*(1.0f/D_);
    float sn = dv*rsqrtf(var+1e-5f)*g_s[d] + be_s[d];
    ssn[d]=sn;
    __syncthreads();

    float q0=0,q1=0,k0=0,k1=0,v0=0,v1=0;
    #pragma unroll 4
    for(int e=0;e<D_;e+=2){
        float s0 = ssn[e], s1 = ssn[e+1];
        q0 = fmaf(s0, w_q[e*D_+d], q0);      q1 = fmaf(s1, w_q[(e+1)*D_+d], q1);
        k0 = fmaf(s0, w_k[e*D_+d], k0);      k1 = fmaf(s1, w_k[(e+1)*D_+d], k1);
        v0 = fmaf(s0, w_v[e*D_+d], v0);      v1 = fmaf(s1, w_v[(e+1)*D_+d], v1);
    }
    float q = q0+q1+b_q[d];
    g_q [row*D_+d]=q;
    g_k [row*D_+d]=k0+k1+b_k[d];
    g_vv[row*D_+d]=v0+v1+b_v[d];
    sq[d]=q;
    __syncthreads();

    float a0=0,a1=0,a2=0,a3=0;
    #pragma unroll 4
    for(int e2=0;e2<D_;e2+=4){
        a0 = fmaf(sq[e2+0], w_d2[d*D_+e2+0], a0);
        a1 = fmaf(sq[e2+1], w_d2[d*D_+e2+1], a1);
        a2 = fmaf(sq[e2+2], w_d2[d*D_+e2+2], a2);
        a3 = fmaf(sq[e2+3], w_d2[d*D_+e2+3], a3);
    }
    g_qd[row*D_+d]=(a0+a1)+(a2+a3);

    float pb = blockSum(q*b_d2[d], red);
    if(d==0) g_qdb[row]=pb;
}

// ---------------- Kernel B: fused attention + all epilogues, one row/block --
__global__ void __launch_bounds__(128) main_kernel(
    const float* __restrict__ scalar, const float* __restrict__ vector,
    const float* __restrict__ coords,
    const float* __restrict__ w_d1, const float* __restrict__ b_d1,
    const float* __restrict__ w_d2, const float* __restrict__ b_d2,
    const float* __restrict__ w_g,  const float* __restrict__ b_g,
    const float* __restrict__ w_o,  const float* __restrict__ b_o,
    const float* __restrict__ w_f1, const float* __restrict__ b_f1,
    const float* __restrict__ w_f2, const float* __restrict__ b_f2,
    const float* __restrict__ w_vo, const float* __restrict__ b_vo,
    const float* __restrict__ g_s,  const float* __restrict__ be_s,
    const float* __restrict__ g_v_, const float* __restrict__ be_v,
    float* __restrict__ out_scalar, float* __restrict__ out_vector)
{
    __shared__ float sq[D_], sqd[D_];
    __shared__ float scoord[N_*3];
    __shared__ float sdist[N_], srd[N_], slog[N_];
    __shared__ float sHm[4][D_], sVm[4][D_];
    __shared__ float sSum[4];
    __shared__ float sH[D_], sbuf[D_], sscal[D_], shn[D_], sf[2*D_];
    __shared__ float svagg2[96], sdirp[24], sdir[3], sgate[V_], sagg[48], svagg[48];
    __shared__ float red[4];

    const int row  = blockIdx.x;
    const int b    = row >> 9;
    const int i    = row & (N_-1);
    const int tid  = threadIdx.x;
    const int warp = tid>>5, lane = tid&31;
    const int half = lane>>4, hl = lane&15;

    sq [tid] = g_q [row*D_+tid];
    sqd[tid] = g_qd[row*D_+tid];
    const float* cb = coords + (size_t)b*N_*3;
    for(int t=tid; t<N_*3; t+=128) scoord[t]=cb[t];
    const float invS = 0.0883883476483184f; // 1/sqrt(128)
    const float qdbS = g_qdb[row]*invS;
    __syncthreads();

    const float ci0 = scoord[i*3+0], ci1 = scoord[i*3+1], ci2 = scoord[i*3+2];

    // ---- pre-pass: all 512 dists (+ reciprocal) once ----
    for(int j=tid; j<N_; j+=128){
        float dx = ci0 - scoord[j*3+0];
        float dy = ci1 - scoord[j*3+1];
        float dz = ci2 - scoord[j*3+2];
        float dist = sqrtf(fmaf(dx,dx,fmaf(dy,dy,dz*dz)));
        sdist[j] = dist;
        srd[j]   = __fdividef(1.0f, fmaxf(dist, 1e-6f));
    }
    __syncthreads();

    const float* kb   = g_k  + (size_t)b*N_*D_;
    const float* vvb  = g_vv + (size_t)b*N_*D_;
    const float* vecb = vector + (size_t)b*N_*3*V_;

    // per-lane constants: d = hl*8 + c
    float qr[8], qdr[8], w1r[8];
    {
        const float4* p;
        p=(const float4*)sq;   float4 a=p[hl*2], bb=p[hl*2+1];
        qr[0]=a.x;qr[1]=a.y;qr[2]=a.z;qr[3]=a.w; qr[4]=bb.x;qr[5]=bb.y;qr[6]=bb.z;qr[7]=bb.w;
        p=(const float4*)sqd;  a=p[hl*2]; bb=p[hl*2+1];
        qdr[0]=a.x;qdr[1]=a.y;qdr[2]=a.z;qdr[3]=a.w; qdr[4]=bb.x;qdr[5]=bb.y;qdr[6]=bb.z;qdr[7]=bb.w;
        p=(const float4*)w_d1; a=p[hl*2]; bb=p[hl*2+1];
        w1r[0]=a.x;w1r[1]=a.y;w1r[2]=a.z;w1r[3]=a.w; w1r[4]=bb.x;w1r[5]=bb.y;w1r[6]=bb.z;w1r[7]=bb.w;
    }
    float b1r[8];
    {
        const float4* p=(const float4*)b_d1; float4 a=p[hl*2], bb=p[hl*2+1];
        b1r[0]=a.x;b1r[1]=a.y;b1r[2]=a.z;b1r[3]=a.w; b1r[4]=bb.x;b1r[5]=bb.y;b1r[6]=bb.z;b1r[7]=bb.w;
    }

    // ---- single fused pass: 2 j's per warp-iter (16 lanes each, 8 d's/lane)
    float Hc[8]={0,0,0,0,0,0,0,0}, Vc[8]={0,0,0,0,0,0,0,0};
    float sacc = 0.0f;

    for(int base = warp*2; base < N_; base += 8){
        const int j = base + half;
        const float dist = sdist[j];

        const float4* krow = (const float4*)(kb + (size_t)j*D_);
        const float4* vrow = (const float4*)(vvb + (size_t)j*D_);
        float4 ka = krow[hl*2], kb4 = krow[hl*2+1];
        float4 va = vrow[hl*2], vb4 = vrow[hl*2+1];
        float kr[8] = {ka.x,ka.y,ka.z,ka.w,kb4.x,kb4.y,kb4.z,kb4.w};
        float vr[8] = {va.x,va.y,va.z,va.w,vb4.x,vb4.y,vb4.z,vb4.w};

        float hh[8];
        float p = 0.0f;
        #pragma unroll
        for(int c=0;c<8;c++){
            hh[c] = gelu_fast(fmaf(dist, w1r[c], b1r[c]));
            p = fmaf(qr[c], kr[c], p);
            p = fmaf(qdr[c], hh[c], p);
        }
        p += __shfl_xor_sync(0xffffffffu, p, 8);
        p += __shfl_xor_sync(0xffffffffu, p, 4);
        p += __shfl_xor_sync(0xffffffffu, p, 2);
        p += __shfl_xor_sync(0xffffffffu, p, 1);

        float e = __expf(fmaf(p, invS, qdbS));
        if(hl==0) slog[j]=e;
        sacc += e;

        #pragma unroll
        for(int c=0;c<8;c++){
            Hc[c] = fmaf(e, hh[c], Hc[c]);
            Vc[c] = fmaf(e, vr[c], Vc[c]);
        }
    }

    // merge halves within warp
    #pragma unroll
    for(int c=0;c<8;c++){
        Hc[c] += __shfl_xor_sync(0xffffffffu, Hc[c], 16);
        Vc[c] += __shfl_xor_sync(0xffffffffu, Vc[c], 16);
    }
    sacc += __shfl_xor_sync(0xffffffffu, sacc, 16);
    if(half==0){
        #pragma unroll
        for(int c=0;c<8;c++){ sHm[warp][hl*8+c]=Hc[c]; sVm[warp][hl*8+c]=Vc[c]; }
    }
    if(lane==0) sSum[warp]=sacc;
    __syncthreads();

    // merge warps + normalize
    const float inv = 1.0f/(sSum[0]+sSum[1]+sSum[2]+sSum[3]);
    float Hd = (sHm[0][tid]+sHm[1][tid]+sHm[2][tid]+sHm[3][tid])*inv;
    float Vd = (sVm[0][tid]+sVm[1][tid]+sVm[2][tid]+sVm[3][tid])*inv;
    sH[tid]=Hd;
    for(int j=tid;j<N_;j+=128) slog[j]*=inv;
    __syncthreads();

    // ---- vector aggregation (96 thr) + direction aggregation (24 thr) ----
    if(tid < 96){
        const int t48 = (tid<48)?tid:(tid-48);
        const int j0  = (tid<48)?0:256;
        float a0=0,a1=0;
        #pragma unroll 4
        for(int j=j0;j<j0+256;j+=2){
            a0 = fmaf(slog[j],   vecb[(size_t)j*48+t48],     a0);
            a1 = fmaf(slog[j+1], vecb[(size_t)(j+1)*48+t48], a1);
        }
        svagg2[tid]=a0+a1;
    } else if(tid < 120){
        const int idx = tid-96, c = idx>>3, g = idx&7;
        const float cic = scoord[i*3+c];
        float acc=0.0f;
        for(int j=g;j<N_;j+=8){
            acc = fmaf(slog[j]*srd[j], cic - scoord[j*3+c], acc);
        }
        sdirp[idx]=acc;
    }
    __syncthreads();
    if(tid<48) svagg[tid]=svagg2[tid]+svagg2[tid+48];
    if(tid<3){
        float a=0;
        #pragma unroll
        for(int g=0;g<8;g++) a+=sdirp[tid*8+g];
        sdir[tid]=a;
    }

    // ---- upd = attn@v + H@w_d2 + b_d2 ----
    {
        float u0=0,u1=0,u2=0,u3=0;
        #pragma unroll 4
        for(int e=0;e<D_;e+=4){
            u0 = fmaf(sH[e+0], w_d2[(e+0)*D_+tid], u0);
            u1 = fmaf(sH[e+1], w_d2[(e+1)*D_+tid], u1);
            u2 = fmaf(sH[e+2], w_d2[(e+2)*D_+tid], u2);
            u3 = fmaf(sH[e+3], w_d2[(e+3)*D_+tid], u3);
        }
        sbuf[tid] = Vd + b_d2[tid] + ((u0+u1)+(u2+u3));
    }
    __syncthreads();

    // ---- scalar1 = scalar + upd@w_o + b_o ----
    float s1;
    {
        float u0=0,u1=0,u2=0,u3=0;
        #pragma unroll 4
        for(int e=0;e<D_;e+=4){
            u0 = fmaf(sbuf[e+0], w_o[(e+0)*D_+tid], u0);
            u1 = fmaf(sbuf[e+1], w_o[(e+1)*D_+tid], u1);
            u2 = fmaf(sbuf[e+2], w_o[(e+2)*D_+tid], u2);
            u3 = fmaf(sbuf[e+3], w_o[(e+3)*D_+tid], u3);
        }
        s1 = scalar[row*D_+tid] + b_o[tid] + ((u0+u1)+(u2+u3));
    }
    sscal[tid]=s1;

    // ---- LN ----
    float m  = blockSum(s1, red)*(1.0f/D_);
    float dv = s1 - m;
    float var= blockSum(dv*dv, red)*(1.0f/D_);
    float hn = dv*rsqrtf(var+1e-5f)*g_s[tid] + be_s[tid];
    shn[tid]=hn;
    __syncthreads();

    // ---- FFN layer 1 ----
    #pragma unroll
    for(int h2=0; h2<2; h2++){
        int m2 = tid + h2*128;
        float u0=0,u1=0,u2=0,u3=0;
        #pragma unroll 4
        for(int e=0;e<D_;e+=4){
            u0 = fmaf(shn[e+0], w_f1[(e+0)*2*D_+m2], u0);
            u1 = fmaf(shn[e+1], w_f1[(e+1)*2*D_+m2], u1);
            u2 = fmaf(shn[e+2], w_f1[(e+2)*2*D_+m2], u2);
            u3 = fmaf(shn[e+3], w_f1[(e+3)*2*D_+m2], u3);
        }
        sf[m2]=geluf(b_f1[m2] + (u0+u1)+(u2+u3));
    }
    __syncthreads();

    // ---- FFN layer 2 ----
    float s2;
    {
        float u0=0,u1=0,u2=0,u3=0;
        #pragma unroll 4
        for(int m2=0;m2<2*D_;m2+=4){
            u0 = fmaf(sf[m2+0], w_f2[(m2+0)*D_+tid], u0);
            u1 = fmaf(sf[m2+1], w_f2[(m2+1)*D_+tid], u1);
            u2 = fmaf(sf[m2+2], w_f2[(m2+2)*D_+tid], u2);
            u3 = fmaf(sf[m2+3], w_f2[(m2+3)*D_+tid], u3);
        }
        s2 = sscal[tid] + b_f2[tid] + ((u0+u1)+(u2+u3));
    }
    out_scalar[row*D_+tid] = s2;
    __syncthreads();
    sscal[tid] = s2;
    __syncthreads();

    // ---- gate ----
    if(tid<V_){
        float u0=0,u1=0,u2=0,u3=0;
        #pragma unroll 4
        for(int d2=0;d2<D_;d2+=4){
            u0 = fmaf(sscal[d2+0], w_g[(d2+0)*V_+tid], u0);
            u1 = fmaf(sscal[d2+1], w_g[(d2+1)*V_+tid], u1);
            u2 = fmaf(sscal[d2+2], w_g[(d2+2)*V_+tid], u2);
            u3 = fmaf(sscal[d2+3], w_g[(d2+3)*V_+tid], u3);
        }
        float a = b_g[tid] + (u0+u1)+(u2+u3);
        sgate[tid] = 1.0f/(1.0f+__expf(-a));
    }
    __syncthreads();

    // ---- agg, LN over V, proj, vector residual ----
    if(tid<48){
        int c = tid>>4, vv = tid&15;
        sagg[tid] = svagg[tid] + sdir[c]*sgate[vv];
    }
    __syncthreads();
    if(tid<48){
        int c = tid>>4, vv = tid&15;
        float m2=0.0f;
        #pragma unroll
        for(int u=0;u<V_;u++) m2 += sagg[c*V_+u];
        m2 *= (1.0f/V_);
        float var2=0.0f;
        #pragma unroll
        for(int u=0;u<V_;u++){ float d3=sagg[c*V_+u]-m2; var2 += d3*d3; }
        var2 *= (1.0f/V_);
        float invr = rsqrtf(var2+1e-5f);
        float acc = b_vo[vv];
        #pragma unroll
        for(int u=0;u<V_;u++){
            float lnu = (sagg[c*V_+u]-m2)*invr*g_v_[u] + be_v[u];
            acc = fmaf(lnu, w_vo[u*V_+vv], acc);
        }
        out_vector[row*3*V_+tid] = vecb[(size_t)i*3*V_+tid] + acc;
    }
}

extern "C" void kernel_launch(void* const* d_in, const int* in_sizes, int n_in,
                              void* d_out, int out_size)
{
    const float* scalar = (const float*)d_in[0];
    const float* vector = (const float*)d_in[1];
    const float* coords = (const float*)d_in[2];
    const float* w_q  = (const float*)d_in[3];  const float* b_q  = (const float*)d_in[4];
    const float* w_k  = (const float*)d_in[5];  const float* b_k  = (const float*)d_in[6];
    const float* w_v  = (const float*)d_in[7];  const float* b_v  = (const float*)d_in[8];
    const float* w_d1 = (const float*)d_in[9];  const float* b_d1 = (const float*)d_in[10];
    const float* w_d2 = (const float*)d_in[11]; const float* b_d2 = (const float*)d_in[12];
    const float* w_g  = (const float*)d_in[13]; const float* b_g  = (const float*)d_in[14];
    const float* w_o  = (const float*)d_in[15]; const float* b_o  = (const float*)d_in[16];
    const float* w_f1 = (const float*)d_in[17]; const float* b_f1 = (const float*)d_in[18];
    const float* w_f2 = (const float*)d_in[19]; const float* b_f2 = (const float*)d_in[20];
    const float* w_vo = (const float*)d_in[21]; const float* b_vo = (const float*)d_in[22];
    const float* g_s  = (const float*)d_in[23]; const float* be_s = (const float*)d_in[24];
    const float* g_v  = (const float*)d_in[25]; const float* be_v = (const float*)d_in[26];

    float* out = (float*)d_out;
    float* out_scalar = out;
    float* out_vector = out + (size_t)ROWS*D_;

    prep_kernel<<<ROWS,128>>>(scalar, w_q,b_q, w_k,b_k, w_v,b_v, w_d2,b_d2, g_s,be_s);
    main_kernel<<<ROWS,128>>>(scalar, vector, coords,
                              w_d1,b_d1, w_d2,b_d2, w_g,b_g, w_o,b_o,
                              w_f1,b_f1, w_f2,b_f2, w_vo,b_vo,
                              g_s,be_s, g_v,be_v,
                              out_scalar, out_vector);
}

// round 4
// speedup vs baseline: 2.4350x; 1.3269x over previous
#include <cuda_runtime.h>
#include <math.h>

#define B_ 2
#define N_ 512
#define D_ 128
#define V_ 16
#define ROWS (B_*N_)

// scratch (allocation-free rule: __device__ globals)
__device__ float g_q  [ROWS*D_];   // q * invS
__device__ float g_k  [ROWS*D_];
__device__ float g_vv [ROWS*D_];
__device__ float g_qc [ROWS*10];   // qc[p]*invS for p=1..10
__device__ float g_bias[ROWS];     // (qc[0] + q.b_d2)*invS

__device__ __forceinline__ float geluf(float x){
    return 0.5f*x*(1.0f+erff(x*0.70710678118654752f));
}
// polynomial coefficients of gelu_fast(w*t+b) in powers of t (degree 10)
__device__ __forceinline__ void gelu_coeffs(float w, float b, float C[11]){
    const float K  = 0.3989422804014327f;
    const float c2 = K;
    const float c4 = K*-0.16666666666667f;
    const float c6 = K*0.025f;
    const float c8 = K*-2.9761904761905e-3f;
    const float c10= K*2.8935185185185e-4f;
    float wp[11], bp[11];
    wp[0]=1.f; bp[0]=1.f;
    #pragma unroll
    for(int t=1;t<11;t++){ wp[t]=wp[t-1]*w; bp[t]=bp[t-1]*b; }
    #pragma unroll
    for(int p=0;p<11;p++) C[p]=0.f;
    C[0] += 0.5f*b; C[1] += 0.5f*w;
    const float B2[3]={1,2,1};
    const float B4[5]={1,4,6,4,1};
    const float B6[7]={1,6,15,20,15,6,1};
    const float B8[9]={1,8,28,56,70,56,28,8,1};
    const float B10[11]={1,10,45,120,210,252,210,120,45,10,1};
    #pragma unroll
    for(int p=0;p<=2;p++)  C[p] += c2 *B2[p] *wp[p]*bp[2-p];
    #pragma unroll
    for(int p=0;p<=4;p++)  C[p] += c4 *B4[p] *wp[p]*bp[4-p];
    #pragma unroll
    for(int p=0;p<=6;p++)  C[p] += c6 *B6[p] *wp[p]*bp[6-p];
    #pragma unroll
    for(int p=0;p<=8;p++)  C[p] += c8 *B8[p] *wp[p]*bp[8-p];
    #pragma unroll
    for(int p=0;p<=10;p++) C[p] += c10*B10[p]*wp[p]*bp[10-p];
}
__device__ __forceinline__ float warpSum(float v){
    #pragma unroll
    for(int o=16;o;o>>=1) v += __shfl_down_sync(0xffffffffu, v, o);
    return v;
}
__device__ __forceinline__ float blockSum(float v, float* red){
    int w = threadIdx.x>>5, l = threadIdx.x&31;
    v = warpSum(v);
    if(l==0) red[w]=v;
    __syncthreads();
    if(threadIdx.x==0) red[0] = red[0]+red[1]+red[2]+red[3];
    __syncthreads();
    float r = red[0];
    __syncthreads();
    return r;
}

// ---------------- Kernel A: LN + q/k/v + qc moments coefficients ----------
__global__ void __launch_bounds__(128) prep_kernel(
    const float* __restrict__ scalar,
    const float* __restrict__ w_q, const float* __restrict__ b_q,
    const float* __restrict__ w_k, const float* __restrict__ b_k,
    const float* __restrict__ w_v, const float* __restrict__ b_v,
    const float* __restrict__ w_d1, const float* __restrict__ b_d1,
    const float* __restrict__ w_d2, const float* __restrict__ b_d2,
    const float* __restrict__ g_s, const float* __restrict__ be_s)
{
    __shared__ float ssn[D_], sq[D_], red[4];
    __shared__ float sWq[4][12];
    const int row = blockIdx.x;
    const int d = threadIdx.x;
    const int warp = d>>5, lane = d&31;
    const float invS = 0.0883883476483184f; // 1/sqrt(128)

    float x = scalar[row*D_+d];
    float m  = blockSum(x, red)*(1.0f/D_);
    float dv = x - m;
    float var= blockSum(dv*dv, red)*(1.0f/D_);
    float sn = dv*rsqrtf(var+1e-5f)*g_s[d] + be_s[d];
    ssn[d]=sn;
    __syncthreads();

    float q0=0,q1=0,k0=0,k1=0,v0=0,v1=0;
    #pragma unroll 4
    for(int e=0;e<D_;e+=2){
        float s0 = ssn[e], s1 = ssn[e+1];
        q0 = fmaf(s0, w_q[e*D_+d], q0);      q1 = fmaf(s1, w_q[(e+1)*D_+d], q1);
        k0 = fmaf(s0, w_k[e*D_+d], k0);      k1 = fmaf(s1, w_k[(e+1)*D_+d], k1);
        v0 = fmaf(s0, w_v[e*D_+d], v0);      v1 = fmaf(s1, w_v[(e+1)*D_+d], v1);
    }
    float q = q0+q1+b_q[d];
    g_q [row*D_+d]=q*invS;
    g_k [row*D_+d]=k0+k1+b_k[d];
    g_vv[row*D_+d]=v0+v1+b_v[d];
    sq[d]=q;
    __syncthreads();

    // qd[e] = sum_d w_d2[e,d]*q[d]  (thread index = e)
    float a0=0,a1=0,a2=0,a3=0;
    #pragma unroll 4
    for(int e2=0;e2<D_;e2+=4){
        a0 = fmaf(sq[e2+0], w_d2[d*D_+e2+0], a0);
        a1 = fmaf(sq[e2+1], w_d2[d*D_+e2+1], a1);
        a2 = fmaf(sq[e2+2], w_d2[d*D_+e2+2], a2);
        a3 = fmaf(sq[e2+3], w_d2[d*D_+e2+3], a3);
    }
    float qd = (a0+a1)+(a2+a3);

    // per-thread poly coefficients of gelu(w_d1[e]*t + b_d1[e])
    float C[11];
    gelu_coeffs(w_d1[d], b_d1[d], C);

    // 12 reductions: qc[p] = sum_e qd[e]*C[p][e], and qdb = q.b_d2
    #pragma unroll
    for(int p=0;p<11;p++){
        float t = warpSum(qd*C[p]);
        if(lane==0) sWq[warp][p]=t;
    }
    {
        float t = warpSum(q*b_d2[d]);
        if(lane==0) sWq[warp][11]=t;
    }
    __syncthreads();
    if(d==0){
        float qc0 = sWq[0][0]+sWq[1][0]+sWq[2][0]+sWq[3][0];
        float qdb = sWq[0][11]+sWq[1][11]+sWq[2][11]+sWq[3][11];
        g_bias[row] = (qc0+qdb)*invS;
    } else if(d<11){
        float qcp = sWq[0][d]+sWq[1][d]+sWq[2][d]+sWq[3][d];
        g_qc[row*10 + (d-1)] = qcp*invS;
    }
}

// ---------------- Kernel B: fused attention + all epilogues, one row/block --
__global__ void __launch_bounds__(128) main_kernel(
    const float* __restrict__ scalar, const float* __restrict__ vector,
    const float* __restrict__ coords,
    const float* __restrict__ w_d1, const float* __restrict__ b_d1,
    const float* __restrict__ w_d2, const float* __restrict__ b_d2,
    const float* __restrict__ w_g,  const float* __restrict__ b_g,
    const float* __restrict__ w_o,  const float* __restrict__ b_o,
    const float* __restrict__ w_f1, const float* __restrict__ b_f1,
    const float* __restrict__ w_f2, const float* __restrict__ b_f2,
    const float* __restrict__ w_vo, const float* __restrict__ b_vo,
    const float* __restrict__ g_s,  const float* __restrict__ be_s,
    const float* __restrict__ g_v_, const float* __restrict__ be_v,
    float* __restrict__ out_scalar, float* __restrict__ out_vector)
{
    __shared__ float sq[D_];
    __shared__ float scoord[N_*3];
    __shared__ float sdist[N_], srd[N_], slog[N_];
    __shared__ float sVm[4][D_];
    __shared__ float sMm[4][10];
    __shared__ float sMn[10];
    __shared__ float sSum[4];
    __shared__ float sH[D_], sbuf[D_], sscal[D_], shn[D_], sf[2*D_];
    __shared__ float svagg2[96], sdirp[24], sdir[3], sgate[V_], sagg[48], svagg[48];
    __shared__ float red[4];

    const int row  = blockIdx.x;
    const int b    = row >> 9;
    const int i    = row & (N_-1);
    const int tid  = threadIdx.x;
    const int warp = tid>>5, lane = tid&31;
    const int half = lane>>4, hl = lane&15;

    sq[tid] = g_q[row*D_+tid];
    const float* cb = coords + (size_t)b*N_*3;
    for(int t=tid; t<N_*3; t+=128) scoord[t]=cb[t];
    const float biasRow = g_bias[row];
    __syncthreads();

    const float ci0 = scoord[i*3+0], ci1 = scoord[i*3+1], ci2 = scoord[i*3+2];

    // ---- pre-pass: all 512 dists (+ reciprocal) ----
    for(int j=tid; j<N_; j+=128){
        float dx = ci0 - scoord[j*3+0];
        float dy = ci1 - scoord[j*3+1];
        float dz = ci2 - scoord[j*3+2];
        float dist = sqrtf(fmaf(dx,dx,fmaf(dy,dy,dz*dz)));
        sdist[j] = dist;
        srd[j]   = __fdividef(1.0f, fmaxf(dist, 1e-6f));
    }
    __syncthreads();

    const float* kb   = g_k  + (size_t)b*N_*D_;
    const float* vvb  = g_vv + (size_t)b*N_*D_;
    const float* vecb = vector + (size_t)b*N_*3*V_;

    // per-lane constants: d = hl*8 + c, moment index p = hl+1 (hl<10)
    float qr[8];
    {
        const float4* p=(const float4*)sq;
        float4 a=p[hl*2], bb=p[hl*2+1];
        qr[0]=a.x;qr[1]=a.y;qr[2]=a.z;qr[3]=a.w; qr[4]=bb.x;qr[5]=bb.y;qr[6]=bb.z;qr[7]=bb.w;
    }
    const int pidx = hl+1;
    const bool u1 = (pidx&1), u2 = (pidx&2), u4 = (pidx&4), u8 = (pidx&8);
    const float qcl = (hl<10) ? g_qc[row*10+hl] : 0.0f;

    // ---- single fused pass: 2 j's per warp-iter (16 lanes each, 8 d's/lane)
    float Vc[8]={0,0,0,0,0,0,0,0};
    float Ml = 0.0f, sacc = 0.0f;

    #pragma unroll 2
    for(int base = warp*2; base < N_; base += 8){
        const int j = base + half;
        const float dist = sdist[j];

        const float4* krow = (const float4*)(kb + (size_t)j*D_);
        const float4* vrow = (const float4*)(vvb + (size_t)j*D_);
        float4 ka = krow[hl*2], kb4 = krow[hl*2+1];
        float4 va = vrow[hl*2], vb4 = vrow[hl*2+1];
        float kr[8] = {ka.x,ka.y,ka.z,ka.w,kb4.x,kb4.y,kb4.z,kb4.w};
        float vr[8] = {va.x,va.y,va.z,va.w,vb4.x,vb4.y,vb4.z,vb4.w};

        // lane's dist power
        float d2 = dist*dist, d4 = d2*d2, d8 = d4*d4;
        float pw = (u1?dist:1.0f);
        pw *= (u2?d2:1.0f);
        pw *= (u4?d4:1.0f);
        pw *= (u8?d8:1.0f);

        float p = qcl*pw;
        #pragma unroll
        for(int c=0;c<8;c++) p = fmaf(qr[c], kr[c], p);

        p += __shfl_xor_sync(0xffffffffu, p, 8);
        p += __shfl_xor_sync(0xffffffffu, p, 4);
        p += __shfl_xor_sync(0xffffffffu, p, 2);
        p += __shfl_xor_sync(0xffffffffu, p, 1);

        float e = __expf(p + biasRow);
        if(hl==0) slog[j]=e;
        sacc += e;
        Ml = fmaf(e, pw, Ml);
        #pragma unroll
        for(int c=0;c<8;c++) Vc[c] = fmaf(e, vr[c], Vc[c]);
    }

    // merge halves within warp
    #pragma unroll
    for(int c=0;c<8;c++) Vc[c] += __shfl_xor_sync(0xffffffffu, Vc[c], 16);
    sacc += __shfl_xor_sync(0xffffffffu, sacc, 16);
    Ml   += __shfl_xor_sync(0xffffffffu, Ml, 16);
    if(half==0){
        #pragma unroll
        for(int c=0;c<8;c++) sVm[warp][hl*8+c]=Vc[c];
        if(hl<10) sMm[warp][hl]=Ml;
    }
    if(lane==0) sSum[warp]=sacc;
    __syncthreads();

    // merge warps + normalize
    const float inv = 1.0f/(sSum[0]+sSum[1]+sSum[2]+sSum[3]);
    float Vd = (sVm[0][tid]+sVm[1][tid]+sVm[2][tid]+sVm[3][tid])*inv;
    if(tid<10) sMn[tid] = (sMm[0][tid]+sMm[1][tid]+sMm[2][tid]+sMm[3][tid])*inv;
    for(int j=tid;j<N_;j+=128) slog[j]*=inv;
    __syncthreads();

    // ---- H reconstruction from moments ----
    {
        float C[11];
        gelu_coeffs(w_d1[tid], b_d1[tid], C);
        float Hd = C[0];
        #pragma unroll
        for(int p=1;p<11;p++) Hd = fmaf(C[p], sMn[p-1], Hd);
        sH[tid]=Hd;
    }

    // ---- vector aggregation (96 thr) + direction aggregation (24 thr) ----
    if(tid < 96){
        const int t48 = (tid<48)?tid:(tid-48);
        const int j0  = (tid<48)?0:256;
        float a0=0,a1=0;
        #pragma unroll 4
        for(int j=j0;j<j0+256;j+=2){
            a0 = fmaf(slog[j],   vecb[(size_t)j*48+t48],     a0);
            a1 = fmaf(slog[j+1], vecb[(size_t)(j+1)*48+t48], a1);
        }
        svagg2[tid]=a0+a1;
    } else if(tid < 120){
        const int idx = tid-96, c = idx>>3, g = idx&7;
        const float cic = scoord[i*3+c];
        float acc=0.0f;
        for(int j=g;j<N_;j+=8){
            acc = fmaf(slog[j]*srd[j], cic - scoord[j*3+c], acc);
        }
        sdirp[idx]=acc;
    }
    __syncthreads();
    if(tid<48) svagg[tid]=svagg2[tid]+svagg2[tid+48];
    if(tid<3){
        float a=0;
        #pragma unroll
        for(int g=0;g<8;g++) a+=sdirp[tid*8+g];
        sdir[tid]=a;
    }

    // ---- upd = attn@v + H@w_d2 + b_d2 ----
    {
        float Vdl = Vd;
        float u0=0,u1=0,u2=0,u3=0;
        #pragma unroll 4
        for(int e=0;e<D_;e+=4){
            u0 = fmaf(sH[e+0], w_d2[(e+0)*D_+tid], u0);
            u1 = fmaf(sH[e+1], w_d2[(e+1)*D_+tid], u1);
            u2 = fmaf(sH[e+2], w_d2[(e+2)*D_+tid], u2);
            u3 = fmaf(sH[e+3], w_d2[(e+3)*D_+tid], u3);
        }
        sbuf[tid] = Vdl + b_d2[tid] + ((u0+u1)+(u2+u3));
    }
    __syncthreads();

    // ---- scalar1 = scalar + upd@w_o + b_o ----
    float s1;
    {
        float u0=0,u1=0,u2=0,u3=0;
        #pragma unroll 4
        for(int e=0;e<D_;e+=4){
            u0 = fmaf(sbuf[e+0], w_o[(e+0)*D_+tid], u0);
            u1 = fmaf(sbuf[e+1], w_o[(e+1)*D_+tid], u1);
            u2 = fmaf(sbuf[e+2], w_o[(e+2)*D_+tid], u2);
            u3 = fmaf(sbuf[e+3], w_o[(e+3)*D_+tid], u3);
        }
        s1 = scalar[row*D_+tid] + b_o[tid] + ((u0+u1)+(u2+u3));
    }
    sscal[tid]=s1;

    // ---- LN ----
    float m  = blockSum(s1, red)*(1.0f/D_);
    float dv = s1 - m;
    float var= blockSum(dv*dv, red)*(1.0f/D_);
    float hn = dv*rsqrtf(var+1e-5f)*g_s[tid] + be_s[tid];
    shn[tid]=hn;
    __syncthreads();

    // ---- FFN layer 1 ----
    #pragma unroll
    for(int h2=0; h2<2; h2++){
        int m2 = tid + h2*128;
        float u0=0,u1=0,u2=0,u3=0;
        #pragma unroll 4
        for(int e=0;e<D_;e+=4){
            u0 = fmaf(shn[e+0], w_f1[(e+0)*2*D_+m2], u0);
            u1 = fmaf(shn[e+1], w_f1[(e+1)*2*D_+m2], u1);
            u2 = fmaf(shn[e+2], w_f1[(e+2)*2*D_+m2], u2);
            u3 = fmaf(shn[e+3], w_f1[(e+3)*2*D_+m2], u3);
        }
        sf[m2]=geluf(b_f1[m2] + (u0+u1)+(u2+u3));
    }
    __syncthreads();

    // ---- FFN layer 2 ----
    float s2;
    {
        float u0=0,u1=0,u2=0,u3=0;
        #pragma unroll 4
        for(int m2=0;m2<2*D_;m2+=4){
            u0 = fmaf(sf[m2+0], w_f2[(m2+0)*D_+tid], u0);
            u1 = fmaf(sf[m2+1], w_f2[(m2+1)*D_+tid], u1);
            u2 = fmaf(sf[m2+2], w_f2[(m2+2)*D_+tid], u2);
            u3 = fmaf(sf[m2+3], w_f2[(m2+3)*D_+tid], u3);
        }
        s2 = sscal[tid] + b_f2[tid] + ((u0+u1)+(u2+u3));
    }
    out_scalar[row*D_+tid] = s2;
    __syncthreads();
    sscal[tid] = s2;
    __syncthreads();

    // ---- gate ----
    if(tid<V_){
        float u0=0,u1=0,u2=0,u3=0;
        #pragma unroll 4
        for(int d2=0;d2<D_;d2+=4){
            u0 = fmaf(sscal[d2+0], w_g[(d2+0)*V_+tid], u0);
            u1 = fmaf(sscal[d2+1], w_g[(d2+1)*V_+tid], u1);
            u2 = fmaf(sscal[d2+2], w_g[(d2+2)*V_+tid], u2);
            u3 = fmaf(sscal[d2+3], w_g[(d2+3)*V_+tid], u3);
        }
        float a = b_g[tid] + (u0+u1)+(u2+u3);
        sgate[tid] = 1.0f/(1.0f+__expf(-a));
    }
    __syncthreads();

    // ---- agg, LN over V, proj, vector residual ----
    if(tid<48){
        int c = tid>>4, vv = tid&15;
        sagg[tid] = svagg[tid] + sdir[c]*sgate[vv];
    }
    __syncthreads();
    if(tid<48){
        int c = tid>>4, vv = tid&15;
        float m2=0.0f;
        #pragma unroll
        for(int u=0;u<V_;u++) m2 += sagg[c*V_+u];
        m2 *= (1.0f/V_);
        float var2=0.0f;
        #pragma unroll
        for(int u=0;u<V_;u++){ float d3=sagg[c*V_+u]-m2; var2 += d3*d3; }
        var2 *= (1.0f/V_);
        float invr = rsqrtf(var2+1e-5f);
        float acc = b_vo[vv];
        #pragma unroll
        for(int u=0;u<V_;u++){
            float lnu = (sagg[c*V_+u]-m2)*invr*g_v_[u] + be_v[u];
            acc = fmaf(lnu, w_vo[u*V_+vv], acc);
        }
        out_vector[row*3*V_+tid] = vecb[(size_t)i*3*V_+tid] + acc;
    }
}

extern "C" void kernel_launch(void* const* d_in, const int* in_sizes, int n_in,
                              void* d_out, int out_size)
{
    const float* scalar = (const float*)d_in[0];
    const float* vector = (const float*)d_in[1];
    const float* coords = (const float*)d_in[2];
    const float* w_q  = (const float*)d_in[3];  const float* b_q  = (const float*)d_in[4];
    const float* w_k  = (const float*)d_in[5];  const float* b_k  = (const float*)d_in[6];
    const float* w_v  = (const float*)d_in[7];  const float* b_v  = (const float*)d_in[8];
    const float* w_d1 = (const float*)d_in[9];  const float* b_d1 = (const float*)d_in[10];
    const float* w_d2 = (const float*)d_in[11]; const float* b_d2 = (const float*)d_in[12];
    const float* w_g  = (const float*)d_in[13]; const float* b_g  = (const float*)d_in[14];
    const float* w_o  = (const float*)d_in[15]; const float* b_o  = (const float*)d_in[16];
    const float* w_f1 = (const float*)d_in[17]; const float* b_f1 = (const float*)d_in[18];
    const float* w_f2 = (const float*)d_in[19]; const float* b_f2 = (const float*)d_in[20];
    const float* w_vo = (const float*)d_in[21]; const float* b_vo = (const float*)d_in[22];
    const float* g_s  = (const float*)d_in[23]; const float* be_s = (const float*)d_in[24];
    const float* g_v  = (const float*)d_in[25]; const float* be_v = (const float*)d_in[26];

    float* out = (float*)d_out;
    float* out_scalar = out;
    float* out_vector = out + (size_t)ROWS*D_;

    prep_kernel<<<ROWS,128>>>(scalar, w_q,b_q, w_k,b_k, w_v,b_v,
                              w_d1,b_d1, w_d2,b_d2, g_s,be_s);
    main_kernel<<<ROWS,128>>>(scalar, vector, coords,
                              w_d1,b_d1, w_d2,b_d2, w_g,b_g, w_o,b_o,
                              w_f1,b_f1, w_f2,b_f2, w_vo,b_vo,
                              g_s,be_s, g_v,be_v,
                              out_scalar, out_vector);
}